// round 5
// baseline (speedup 1.0000x reference)
#include <cuda_runtime.h>

#define NPTS 131072
#define NM   34
#define NK   15
#define CIN  32
#define COUT 64
#define PTS_PER_BLOCK 8
#define NWARPS 4
#define PTS_PER_WARP 2
#define NTHREADS 128
#define INV_SIGMA 25.0f          // 1 / 0.04
#define BN_EPS 1e-5f
#define NEG_SLOPE 0.2f

// ---- device scratch (no allocations allowed) ----
__device__ float g_raw[(size_t)NPTS * COUT];   // pre-BN conv output
__device__ float g_accum[2 * COUT];            // per-channel sum / sumsq
__device__ float g_params[2 * COUT];           // scale / shift

__global__ void zero_accum_kernel() {
    int t = threadIdx.x;
    if (t < 2 * COUT) g_accum[t] = 0.f;
}

__global__ __launch_bounds__(NTHREADS)
void kpconv_main(const float* __restrict__ xyz,
                 const float* __restrict__ feats,
                 const int*   __restrict__ nbr,
                 const float* __restrict__ weight,
                 const float* __restrict__ kpts)
{
    // ---- static shared memory (~27KB, no opt-in needed) ----
    __shared__ float  sm_wf[PTS_PER_BLOCK * 480];   // 15360 B
    __shared__ float4 sm_kc[16];                    //   256 B
    __shared__ float  sm_bn[2 * COUT];              //   512 B
    __shared__ float4 sm_nb[NWARPS][NM];            //  2176 B
    __shared__ int    sm_idx[NWARPS][NM];           //   544 B
    __shared__ float  sm_w[NWARPS][512];            //  8192 B

    const int tid  = threadIdx.x;
    const int lane = tid & 31;
    const int warp = tid >> 5;

    if (tid < 16) {
        float4 kc = make_float4(0.f, 0.f, 0.f, 0.f);
        if (tid < NK) {
            kc.x = kpts[tid * 3 + 0];
            kc.y = kpts[tid * 3 + 1];
            kc.z = kpts[tid * 3 + 2];
        }
        sm_kc[tid] = kc;
    }
    if (tid < 2 * COUT) sm_bn[tid] = 0.f;
    __syncthreads();

    // ---------------- stage 1: per-point wf[15][32] ----------------
    for (int i = 0; i < PTS_PER_WARP; i++) {
        const int pt = warp * PTS_PER_WARP + i;
        const int n  = blockIdx.x * PTS_PER_BLOCK + pt;

        const float cx = xyz[n * 3 + 0];
        const float cy = xyz[n * 3 + 1];
        const float cz = xyz[n * 3 + 2];

        // neighbor prep: offsets + clamped feature indices
        #pragma unroll
        for (int j = 0; j < 2; j++) {
            int m = j * 32 + lane;
            if (m < NM) {
                int idx = nbr[n * NM + m];
                int ci  = (idx < NPTS) ? idx : 0;          // shadow guard
                float nx = xyz[ci * 3 + 0] - cx;
                float ny = xyz[ci * 3 + 1] - cy;
                float nz = xyz[ci * 3 + 2] - cz;
                if (idx >= NPTS) { nx = 1e6f; ny = 1e6f; nz = 1e6f; }
                sm_nb[warp][m]  = make_float4(nx, ny, nz, 0.f);
                sm_idx[warp][m] = ci;
            }
        }
        __syncwarp();

        // all 510 (m,k) influence weights, pair-parallel across lanes
        #pragma unroll
        for (int it = 0; it < 16; it++) {
            int p = it * 32 + lane;                        // 0..511
            int k = (int)((unsigned)p / 34u);              // <=15 (pad row)
            int m = p - k * 34;
            float4 nb = sm_nb[warp][m];
            float4 kc = sm_kc[k];                          // kc[15] = zeros
            float dx = nb.x - kc.x;
            float dy = nb.y - kc.y;
            float dz = nb.z - kc.z;
            float d2 = fmaf(dx, dx, fmaf(dy, dy, dz * dz));
            float w  = fmaxf(0.f, fmaf(sqrtf(d2), -INV_SIGMA, 1.f));
            sm_w[warp][p] = w;                             // p=510,511 unused
        }
        __syncwarp();

        // wf[k] accumulation, lane = input channel
        float wf[NK];
        #pragma unroll
        for (int k = 0; k < NK; k++) wf[k] = 0.f;

        #pragma unroll 2
        for (int m = 0; m < NM; m++) {
            int ci  = sm_idx[warp][m];
            float f = __ldg(&feats[ci * CIN + lane]);
            #pragma unroll
            for (int k = 0; k < NK; k++)
                wf[k] = fmaf(sm_w[warp][k * 34 + m], f, wf[k]);
        }

        #pragma unroll
        for (int k = 0; k < NK; k++)
            sm_wf[pt * 480 + k * 32 + lane] = wf[k];
        __syncwarp();
    }
    __syncthreads();

    // ---------------- stage 2: GEMM wf[8][480] @ W[480][64] ----------------
    const int tx = tid & 15;   // output-channel quad (4*tx .. 4*tx+3)
    const int ty = tid >> 4;   // point 0..7

    float acc[4] = {0.f, 0.f, 0.f, 0.f};

    const float4* Wv = (const float4*)weight;                 // [480][16]
    const float4* Av = (const float4*)(sm_wf + ty * 480);     // [120]

    #pragma unroll 4
    for (int kc4 = 0; kc4 < 120; kc4++) {
        float4 a = Av[kc4];                                   // LDS.128 bcast
        const float* pa = (const float*)&a;
        #pragma unroll
        for (int u = 0; u < 4; u++) {
            float4 b = __ldg(&Wv[(kc4 * 4 + u) * 16 + tx]);
            float s = pa[u];
            acc[0] = fmaf(s, b.x, acc[0]);
            acc[1] = fmaf(s, b.y, acc[1]);
            acc[2] = fmaf(s, b.z, acc[2]);
            acc[3] = fmaf(s, b.w, acc[3]);
        }
    }

    // raw output + BN partial sums
    const int n = blockIdx.x * PTS_PER_BLOCK + ty;
    *(float4*)&g_raw[(size_t)n * COUT + tx * 4] =
        make_float4(acc[0], acc[1], acc[2], acc[3]);

    #pragma unroll
    for (int j = 0; j < 4; j++) {
        atomicAdd(&sm_bn[tx * 4 + j], acc[j]);
        atomicAdd(&sm_bn[COUT + tx * 4 + j], acc[j] * acc[j]);
    }
    __syncthreads();
    if (tid < 2 * COUT) atomicAdd(&g_accum[tid], sm_bn[tid]);
}

__global__ void bn_stats_kernel(const float* __restrict__ gamma,
                                const float* __restrict__ beta)
{
    int d = threadIdx.x;
    if (d >= COUT) return;
    const float invN = 1.0f / (float)NPTS;
    float mean = g_accum[d] * invN;
    float var  = g_accum[COUT + d] * invN - mean * mean;
    float inv  = 1.0f / sqrtf(var + BN_EPS);
    float sc   = gamma[d] * inv;
    g_params[d]        = sc;
    g_params[COUT + d] = fmaf(-mean, sc, beta[d]);
}

__global__ __launch_bounds__(256)
void finalize_kernel(float* __restrict__ out)
{
    int i = blockIdx.x * blockDim.x + threadIdx.x;   // over N*64/4 float4s
    float4 v = *(const float4*)&g_raw[(size_t)i * 4];
    int d4 = i & 15;                                 // channel quad
    const float4* p4 = (const float4*)g_params;
    float4 sc = p4[d4];
    float4 sh = p4[16 + d4];
    float x0 = fmaf(v.x, sc.x, sh.x);
    float x1 = fmaf(v.y, sc.y, sh.y);
    float x2 = fmaf(v.z, sc.z, sh.z);
    float x3 = fmaf(v.w, sc.w, sh.w);
    x0 = (x0 >= 0.f) ? x0 : NEG_SLOPE * x0;
    x1 = (x1 >= 0.f) ? x1 : NEG_SLOPE * x1;
    x2 = (x2 >= 0.f) ? x2 : NEG_SLOPE * x2;
    x3 = (x3 >= 0.f) ? x3 : NEG_SLOPE * x3;
    ((float4*)out)[i] = make_float4(x0, x1, x2, x3);
}

extern "C" void kernel_launch(void* const* d_in, const int* in_sizes, int n_in,
                              void* d_out, int out_size)
{
    const float* xyz    = (const float*)d_in[0];
    const float* feats  = (const float*)d_in[1];
    const int*   nbr    = (const int*)d_in[2];
    const float* weight = (const float*)d_in[3];
    const float* kpts   = (const float*)d_in[4];
    const float* gamma  = (const float*)d_in[5];
    const float* beta   = (const float*)d_in[6];
    float* out = (float*)d_out;

    zero_accum_kernel<<<1, 128>>>();
    kpconv_main<<<NPTS / PTS_PER_BLOCK, NTHREADS>>>(xyz, feats, nbr, weight, kpts);
    bn_stats_kernel<<<1, 64>>>(gamma, beta);
    finalize_kernel<<<(NPTS * COUT / 4) / 256, 256>>>(out);
}

// round 6
// speedup vs baseline: 1.8498x; 1.8498x over previous
#include <cuda_runtime.h>

#define NPTS 131072
#define NM   34
#define NK   15
#define CIN  32
#define COUT 64
#define KTOT 480                 // NK * CIN
#define INV_SIGMA 25.0f          // 1 / 0.04
#define BN_EPS 1e-5f
#define NEG_SLOPE 0.2f

// ---- device scratch (no allocations allowed) ----
__device__ float g_wf[(size_t)NPTS * KTOT];    // stage-1 output  (252 MB)
__device__ float g_raw[(size_t)NPTS * COUT];   // pre-BN conv out (33.5 MB)
__device__ float g_accum[2 * COUT];            // per-channel sum / sumsq
__device__ float g_params[2 * COUT];           // scale / shift

// ---- packed f32x2 helpers ----
__device__ __forceinline__ unsigned long long ffma2(unsigned long long a,
                                                    unsigned long long b,
                                                    unsigned long long c) {
    unsigned long long d;
    asm("fma.rn.f32x2 %0, %1, %2, %3;" : "=l"(d) : "l"(a), "l"(b), "l"(c));
    return d;
}
__device__ __forceinline__ unsigned long long pack2(float lo, float hi) {
    unsigned long long d;
    asm("mov.b64 %0, {%1, %2};" : "=l"(d) : "f"(lo), "f"(hi));
    return d;
}
__device__ __forceinline__ void unpack2(unsigned long long v, float& lo, float& hi) {
    asm("mov.b64 {%0, %1}, %2;" : "=f"(lo), "=f"(hi) : "l"(v));
}

__global__ void zero_accum_kernel() {
    int t = threadIdx.x;
    if (t < 2 * COUT) g_accum[t] = 0.f;
}

// ================= stage 1: wf[n][k*32+c] =================
// 128 threads, 4 warps, 2 points per warp, lane = input channel
__global__ __launch_bounds__(128)
void kpconv_wf(const float* __restrict__ xyz,
               const float* __restrict__ feats,
               const int*   __restrict__ nbr,
               const float* __restrict__ kpts)
{
    __shared__ float4 sm_kc[16];
    __shared__ float4 sm_nb[4][NM];
    __shared__ int    sm_idx[4][NM];
    __shared__ __align__(16) float sm_w[4][NM * 16];   // m-major, k stride 1 (k=15 pad)

    const int tid  = threadIdx.x;
    const int lane = tid & 31;
    const int warp = tid >> 5;

    if (tid < 16) {
        float4 kc = make_float4(0.f, 0.f, 0.f, 0.f);
        if (tid < NK) {
            kc.x = kpts[tid * 3 + 0];
            kc.y = kpts[tid * 3 + 1];
            kc.z = kpts[tid * 3 + 2];
        }
        sm_kc[tid] = kc;
    }
    __syncthreads();

    #pragma unroll
    for (int i = 0; i < 2; i++) {
        const int n = blockIdx.x * 8 + warp * 2 + i;

        const float cx = xyz[n * 3 + 0];
        const float cy = xyz[n * 3 + 1];
        const float cz = xyz[n * 3 + 2];

        // neighbor prep
        #pragma unroll
        for (int j = 0; j < 2; j++) {
            int m = j * 32 + lane;
            if (m < NM) {
                int idx = nbr[n * NM + m];
                int ci  = (idx < NPTS) ? idx : 0;          // shadow guard
                float nx = xyz[ci * 3 + 0] - cx;
                float ny = xyz[ci * 3 + 1] - cy;
                float nz = xyz[ci * 3 + 2] - cz;
                if (idx >= NPTS) { nx = 1e6f; ny = 1e6f; nz = 1e6f; }
                sm_nb[warp][m]  = make_float4(nx, ny, nz, 0.f);
                sm_idx[warp][m] = ci;
            }
        }
        __syncwarp();

        // influence weights, m-major layout w[m*16 + k]; k==15 is a zero pad
        #pragma unroll
        for (int it = 0; it < 17; it++) {
            int p = it * 32 + lane;                        // 0..543
            int m = p >> 4;
            int k = p & 15;
            float4 nb = sm_nb[warp][m];
            float4 kc = sm_kc[k];
            float dx = nb.x - kc.x;
            float dy = nb.y - kc.y;
            float dz = nb.z - kc.z;
            float d2 = fmaf(dx, dx, fmaf(dy, dy, dz * dz));
            float w  = fmaxf(0.f, fmaf(sqrtf(d2), -INV_SIGMA, 1.f));
            sm_w[warp][p] = (k == 15) ? 0.f : w;
        }
        __syncwarp();

        // wf accumulation: 8 packed pairs (k0,k1)..(k14,pad)
        unsigned long long wf2[8];
        #pragma unroll
        for (int j = 0; j < 8; j++) wf2[j] = 0ull;

        #pragma unroll 2
        for (int m = 0; m < NM; m++) {
            int ci  = sm_idx[warp][m];
            float f = __ldg(&feats[ci * CIN + lane]);
            unsigned long long ff = pack2(f, f);
            const unsigned long long* wp =
                (const unsigned long long*)&sm_w[warp][m * 16];
            #pragma unroll
            for (int j = 0; j < 8; j++)
                wf2[j] = ffma2(ff, wp[j], wf2[j]);
        }

        // store (k-major global layout: col = k*32 + lane)
        float* dst = &g_wf[(size_t)n * KTOT];
        #pragma unroll
        for (int j = 0; j < 8; j++) {
            float lo, hi;
            unpack2(wf2[j], lo, hi);
            dst[(2 * j) * 32 + lane] = lo;
            if (j < 7) dst[(2 * j + 1) * 32 + lane] = hi;
        }
        __syncwarp();
    }
}

// ================= stage 2: GEMM [N,480] @ [480,64] =================
#define BM 128
#define BK 16
#define BN 64

__global__ __launch_bounds__(256)
void gemm_kernel(const float* __restrict__ weight)
{
    __shared__ __align__(16) float As[BM][BK + 1];   // +1 pad: conflict-free a reads
    __shared__ __align__(16) float Bs[BK][BN];
    __shared__ float sm_bn[2 * COUT];

    const int tid = threadIdx.x;
    const int tx  = tid & 15;        // cout quad: 4*tx .. 4*tx+3
    const int tyB = tid >> 4;        // point group: 8 points
    const int row0 = blockIdx.x * BM;

    if (tid < 2 * COUT) sm_bn[tid] = 0.f;

    unsigned long long acc[8][2];
    #pragma unroll
    for (int i = 0; i < 8; i++) { acc[i][0] = 0ull; acc[i][1] = 0ull; }

    for (int kc = 0; kc < KTOT / BK; kc++) {
        // load A tile 128x16 (2 float4 per thread), store scalar (pad 17)
        #pragma unroll
        for (int q = 0; q < 2; q++) {
            int idx = tid * 2 + q;               // 0..511
            int r   = idx >> 2;
            int c4  = idx & 3;
            float4 v = *(const float4*)&g_wf[(size_t)(row0 + r) * KTOT + kc * BK + c4 * 4];
            As[r][c4 * 4 + 0] = v.x;
            As[r][c4 * 4 + 1] = v.y;
            As[r][c4 * 4 + 2] = v.z;
            As[r][c4 * 4 + 3] = v.w;
        }
        // load B tile 16x64 (1 float4 per thread)
        {
            int r  = tid >> 4;
            int c4 = tid & 15;
            *(float4*)&Bs[r][c4 * 4] =
                __ldg((const float4*)&weight[(size_t)(kc * BK + r) * COUT + c4 * 4]);
        }
        __syncthreads();

        #pragma unroll
        for (int k = 0; k < BK; k++) {
            ulonglong2 b = *(const ulonglong2*)&Bs[k][tx * 4];
            #pragma unroll
            for (int i = 0; i < 8; i++) {
                float a = As[tyB * 8 + i][k];
                unsigned long long aa = pack2(a, a);
                acc[i][0] = ffma2(aa, b.x, acc[i][0]);
                acc[i][1] = ffma2(aa, b.y, acc[i][1]);
            }
        }
        __syncthreads();
    }

    // epilogue: raw out + BN partial sums
    float lsum[4] = {0.f, 0.f, 0.f, 0.f};
    float lsq[4]  = {0.f, 0.f, 0.f, 0.f};
    #pragma unroll
    for (int i = 0; i < 8; i++) {
        float v0, v1, v2, v3;
        unpack2(acc[i][0], v0, v1);
        unpack2(acc[i][1], v2, v3);
        int n = row0 + tyB * 8 + i;
        *(float4*)&g_raw[(size_t)n * COUT + tx * 4] = make_float4(v0, v1, v2, v3);
        lsum[0] += v0; lsum[1] += v1; lsum[2] += v2; lsum[3] += v3;
        lsq[0] = fmaf(v0, v0, lsq[0]);
        lsq[1] = fmaf(v1, v1, lsq[1]);
        lsq[2] = fmaf(v2, v2, lsq[2]);
        lsq[3] = fmaf(v3, v3, lsq[3]);
    }
    #pragma unroll
    for (int j = 0; j < 4; j++) {
        atomicAdd(&sm_bn[tx * 4 + j], lsum[j]);
        atomicAdd(&sm_bn[COUT + tx * 4 + j], lsq[j]);
    }
    __syncthreads();
    if (tid < 2 * COUT) atomicAdd(&g_accum[tid], sm_bn[tid]);
}

// ================= BN stats + finalize =================
__global__ void bn_stats_kernel(const float* __restrict__ gamma,
                                const float* __restrict__ beta)
{
    int d = threadIdx.x;
    if (d >= COUT) return;
    const float invN = 1.0f / (float)NPTS;
    float mean = g_accum[d] * invN;
    float var  = g_accum[COUT + d] * invN - mean * mean;
    float inv  = 1.0f / sqrtf(var + BN_EPS);
    float sc   = gamma[d] * inv;
    g_params[d]        = sc;
    g_params[COUT + d] = fmaf(-mean, sc, beta[d]);
}

__global__ __launch_bounds__(256)
void finalize_kernel(float* __restrict__ out)
{
    int i = blockIdx.x * blockDim.x + threadIdx.x;   // over N*64/4 float4s
    float4 v = *(const float4*)&g_raw[(size_t)i * 4];
    int d4 = i & 15;
    const float4* p4 = (const float4*)g_params;
    float4 sc = p4[d4];
    float4 sh = p4[16 + d4];
    float x0 = fmaf(v.x, sc.x, sh.x);
    float x1 = fmaf(v.y, sc.y, sh.y);
    float x2 = fmaf(v.z, sc.z, sh.z);
    float x3 = fmaf(v.w, sc.w, sh.w);
    x0 = (x0 >= 0.f) ? x0 : NEG_SLOPE * x0;
    x1 = (x1 >= 0.f) ? x1 : NEG_SLOPE * x1;
    x2 = (x2 >= 0.f) ? x2 : NEG_SLOPE * x2;
    x3 = (x3 >= 0.f) ? x3 : NEG_SLOPE * x3;
    ((float4*)out)[i] = make_float4(x0, x1, x2, x3);
}

extern "C" void kernel_launch(void* const* d_in, const int* in_sizes, int n_in,
                              void* d_out, int out_size)
{
    const float* xyz    = (const float*)d_in[0];
    const float* feats  = (const float*)d_in[1];
    const int*   nbr    = (const int*)d_in[2];
    const float* weight = (const float*)d_in[3];
    const float* kpts   = (const float*)d_in[4];
    const float* gamma  = (const float*)d_in[5];
    const float* beta   = (const float*)d_in[6];
    float* out = (float*)d_out;

    zero_accum_kernel<<<1, 128>>>();
    kpconv_wf<<<NPTS / 8, 128>>>(xyz, feats, nbr, kpts);
    gemm_kernel<<<NPTS / BM, 256>>>(weight);
    bn_stats_kernel<<<1, 64>>>(gamma, beta);
    finalize_kernel<<<(NPTS * COUT / 4) / 256, 256>>>(out);
}

// round 9
// speedup vs baseline: 2.3349x; 1.2623x over previous
#include <cuda_runtime.h>
#include <cuda_fp16.h>
#include <stdint.h>

#define NPTS 131072
#define NM   34
#define NK   15
#define CIN  32
#define COUT 64
#define KTOT 480                 // NK * CIN
#define INV_SIGMA 25.0f          // 1 / 0.04
#define BN_EPS 1e-5f
#define NEG_SLOPE 0.2f

// ---- device scratch (no allocations allowed) ----
__device__ __half g_wf_hi[(size_t)NPTS * KTOT];   // 126 MB
__device__ __half g_wf_lo[(size_t)NPTS * KTOT];   // 126 MB
__device__ __half g_wh_hi[KTOT * COUT];           // 60 KB
__device__ __half g_wh_lo[KTOT * COUT];           // 60 KB
__device__ float  g_raw[(size_t)NPTS * COUT];     // 33.5 MB
__device__ float  g_accum[2 * COUT];
__device__ float  g_params[2 * COUT];

// ---- packed f32x2 helpers (stage 1) ----
__device__ __forceinline__ unsigned long long ffma2(unsigned long long a,
                                                    unsigned long long b,
                                                    unsigned long long c) {
    unsigned long long d;
    asm("fma.rn.f32x2 %0, %1, %2, %3;" : "=l"(d) : "l"(a), "l"(b), "l"(c));
    return d;
}
__device__ __forceinline__ unsigned long long pack2(float lo, float hi) {
    unsigned long long d;
    asm("mov.b64 %0, {%1, %2};" : "=l"(d) : "f"(lo), "f"(hi));
    return d;
}
__device__ __forceinline__ void unpack2(unsigned long long v, float& lo, float& hi) {
    asm("mov.b64 {%0, %1}, %2;" : "=f"(lo), "=f"(hi) : "l"(v));
}

// ---- tensor-core helpers ----
__device__ __forceinline__ uint32_t smem_u32(const void* p) {
    return (uint32_t)__cvta_generic_to_shared(p);
}
__device__ __forceinline__ void ldm_x4(uint32_t& r0, uint32_t& r1,
                                       uint32_t& r2, uint32_t& r3, uint32_t addr) {
    asm volatile("ldmatrix.sync.aligned.m8n8.x4.shared.b16 {%0,%1,%2,%3}, [%4];"
                 : "=r"(r0), "=r"(r1), "=r"(r2), "=r"(r3) : "r"(addr));
}
__device__ __forceinline__ void ldm_x4_trans(uint32_t& r0, uint32_t& r1,
                                             uint32_t& r2, uint32_t& r3, uint32_t addr) {
    asm volatile("ldmatrix.sync.aligned.m8n8.x4.trans.shared.b16 {%0,%1,%2,%3}, [%4];"
                 : "=r"(r0), "=r"(r1), "=r"(r2), "=r"(r3) : "r"(addr));
}
__device__ __forceinline__ void mma16816(float& c0, float& c1, float& c2, float& c3,
                                         uint32_t a0, uint32_t a1, uint32_t a2, uint32_t a3,
                                         uint32_t b0, uint32_t b1) {
    asm volatile("mma.sync.aligned.m16n8k16.row.col.f32.f16.f16.f32 "
                 "{%0,%1,%2,%3}, {%4,%5,%6,%7}, {%8,%9}, {%0,%1,%2,%3};"
                 : "+f"(c0), "+f"(c1), "+f"(c2), "+f"(c3)
                 : "r"(a0), "r"(a1), "r"(a2), "r"(a3), "r"(b0), "r"(b1));
}

// ================= stage 1: wf (split fp16) =================
// 128 threads, 4 warps, 2 points per warp, lane = input channel
__global__ __launch_bounds__(128)
void kpconv_wf(const float* __restrict__ xyz,
               const float* __restrict__ feats,
               const int*   __restrict__ nbr,
               const float* __restrict__ kpts,
               const float* __restrict__ weight)
{
    __shared__ float4 sm_kc[16];
    __shared__ float4 sm_nb[4][NM];
    __shared__ int    sm_idx[4][NM];
    __shared__ int    sm_act[4][NM];
    __shared__ __align__(16) float sm_w[4][NM * 16];   // m-major, k stride 1

    const int tid  = threadIdx.x;
    const int lane = tid & 31;
    const int warp = tid >> 5;

    // block 0: one-time prep (W split + accum zero) — replay-safe
    if (blockIdx.x == 0) {
        for (int i = tid; i < KTOT * COUT; i += 128) {
            float w = weight[i];
            __half h = __float2half_rn(w);
            g_wh_hi[i] = h;
            g_wh_lo[i] = __float2half_rn(w - __half2float(h));
        }
        if (tid < 2 * COUT) g_accum[tid] = 0.f;
    }

    if (tid < 16) {
        float4 kc = make_float4(0.f, 0.f, 0.f, 0.f);
        if (tid < NK) {
            kc.x = kpts[tid * 3 + 0];
            kc.y = kpts[tid * 3 + 1];
            kc.z = kpts[tid * 3 + 2];
        }
        sm_kc[tid] = kc;
    }
    __syncthreads();

    #pragma unroll
    for (int i = 0; i < 2; i++) {
        const int n = blockIdx.x * 8 + warp * 2 + i;

        const float cx = xyz[n * 3 + 0];
        const float cy = xyz[n * 3 + 1];
        const float cz = xyz[n * 3 + 2];

        #pragma unroll
        for (int j = 0; j < 2; j++) {
            int m = j * 32 + lane;
            if (m < NM) {
                int idx = nbr[n * NM + m];
                int ci  = (idx < NPTS) ? idx : 0;          // shadow guard
                float nx = xyz[ci * 3 + 0] - cx;
                float ny = xyz[ci * 3 + 1] - cy;
                float nz = xyz[ci * 3 + 2] - cz;
                if (idx >= NPTS) { nx = 1e6f; ny = 1e6f; nz = 1e6f; }
                sm_nb[warp][m]  = make_float4(nx, ny, nz, 0.f);
                sm_idx[warp][m] = ci;
            }
        }
        __syncwarp();

        // influence weights w[m*16+k] + per-m activity mask
        #pragma unroll
        for (int it = 0; it < 17; it++) {
            int p = it * 32 + lane;                        // 0..543
            int m = p >> 4;
            int k = p & 15;
            float4 nb = sm_nb[warp][m];
            float4 kc = sm_kc[k];
            float dx = nb.x - kc.x;
            float dy = nb.y - kc.y;
            float dz = nb.z - kc.z;
            float d2 = fmaf(dx, dx, fmaf(dy, dy, dz * dz));
            float w  = fmaf(sqrtf(d2), -INV_SIGMA, 1.f);
            bool on  = (w > 0.f) && (k < 15);
            unsigned bal = __ballot_sync(0xffffffffu, on);
            sm_w[warp][p] = on ? w : 0.f;
            if (lane == 0)  sm_act[warp][it * 2]     = (int)(bal & 0xffffu);
            if (lane == 16) sm_act[warp][it * 2 + 1] = (int)(bal >> 16);
        }
        __syncwarp();

        // wf accumulation (skip fully-inactive neighbors — warp-uniform branch)
        unsigned long long wf2[8];
        #pragma unroll
        for (int j = 0; j < 8; j++) wf2[j] = 0ull;

        #pragma unroll 2
        for (int m = 0; m < NM; m++) {
            if (sm_act[warp][m] == 0) continue;
            int ci  = sm_idx[warp][m];
            float f = __ldg(&feats[ci * CIN + lane]);
            unsigned long long ff = pack2(f, f);
            const unsigned long long* wp =
                (const unsigned long long*)&sm_w[warp][m * 16];
            #pragma unroll
            for (int j = 0; j < 8; j++)
                wf2[j] = ffma2(ff, wp[j], wf2[j]);
        }

        // split-fp16 store (k-major: col = k*32 + lane)
        __half* dh = &g_wf_hi[(size_t)n * KTOT + lane];
        __half* dl = &g_wf_lo[(size_t)n * KTOT + lane];
        #pragma unroll
        for (int j = 0; j < 8; j++) {
            float a, b;
            unpack2(wf2[j], a, b);
            __half ha = __float2half_rn(a);
            dh[(2 * j) * 32] = ha;
            dl[(2 * j) * 32] = __float2half_rn(a - __half2float(ha));
            if (j < 7) {
                __half hb = __float2half_rn(b);
                dh[(2 * j + 1) * 32] = hb;
                dl[(2 * j + 1) * 32] = __float2half_rn(b - __half2float(hb));
            }
        }
        __syncwarp();
    }
}

// ================= stage 2: HMMA GEMM [N,480]x[480,64], split fp16 =================
// 256 threads = 8 warps; warp w owns rows [16w,16w+16) of a 128-row tile, all 64 cols.
__global__ __launch_bounds__(256)
void gemm_kernel()
{
    __shared__ __align__(16) __half As_hi[128][40];
    __shared__ __align__(16) __half As_lo[128][40];
    __shared__ __align__(16) __half Bs_hi[32][72];
    __shared__ __align__(16) __half Bs_lo[32][72];
    __shared__ float sm_bn[2 * COUT];

    const int tid  = threadIdx.x;
    const int lane = tid & 31;
    const int warp = tid >> 5;
    const int row0 = blockIdx.x * 128;

    if (tid < 2 * COUT) sm_bn[tid] = 0.f;

    float acc[8][4];
    #pragma unroll
    for (int nt = 0; nt < 8; nt++)
        #pragma unroll
        for (int c = 0; c < 4; c++) acc[nt][c] = 0.f;

    // ldmatrix lane address bases
    const int arow = warp * 16 + (lane & 15);
    const int acol = (lane >> 4) * 8;
    const uint32_t aHi = smem_u32(&As_hi[arow][acol]);
    const uint32_t aLo = smem_u32(&As_lo[arow][acol]);
    const int brow = ((lane >> 3) & 1) * 8 + (lane & 7);
    const int bcol = (lane >> 4) * 8;
    const uint32_t bHi = smem_u32(&Bs_hi[brow][bcol]);
    const uint32_t bLo = smem_u32(&Bs_lo[brow][bcol]);

    const int ar = tid >> 2, aq = tid & 3;     // A tile: 4 thr/row, 64 rows/pass
    const int br = tid >> 3, bq = tid & 7;     // B tile: 8 thr/row, 32 rows

    for (int kc = 0; kc < KTOT / 32; kc++) {
        #pragma unroll
        for (int p = 0; p < 2; p++) {
            size_t g = (size_t)(row0 + ar + p * 64) * KTOT + kc * 32 + aq * 8;
            *(uint4*)&As_hi[ar + p * 64][aq * 8] = *(const uint4*)&g_wf_hi[g];
            *(uint4*)&As_lo[ar + p * 64][aq * 8] = *(const uint4*)&g_wf_lo[g];
        }
        {
            size_t g = (size_t)(kc * 32 + br) * COUT + bq * 8;
            *(uint4*)&Bs_hi[br][bq * 8] = *(const uint4*)&g_wh_hi[g];
            *(uint4*)&Bs_lo[br][bq * 8] = *(const uint4*)&g_wh_lo[g];
        }
        __syncthreads();

        #pragma unroll
        for (int ks = 0; ks < 2; ks++) {
            uint32_t ah[4], al[4];
            ldm_x4(ah[0], ah[1], ah[2], ah[3], aHi + ks * 32);   // +16 halves
            ldm_x4(al[0], al[1], al[2], al[3], aLo + ks * 32);

            uint32_t bh[8][2], bl[8][2];
            #pragma unroll
            for (int np = 0; np < 4; np++) {
                uint32_t r0, r1, r2, r3;
                ldm_x4_trans(r0, r1, r2, r3, bHi + ks * 16 * 144 + np * 32);
                bh[2 * np][0] = r0; bh[2 * np][1] = r1;
                bh[2 * np + 1][0] = r2; bh[2 * np + 1][1] = r3;
                ldm_x4_trans(r0, r1, r2, r3, bLo + ks * 16 * 144 + np * 32);
                bl[2 * np][0] = r0; bl[2 * np][1] = r1;
                bl[2 * np + 1][0] = r2; bl[2 * np + 1][1] = r3;
            }
            #pragma unroll
            for (int nt = 0; nt < 8; nt++) {
                mma16816(acc[nt][0], acc[nt][1], acc[nt][2], acc[nt][3],
                         ah[0], ah[1], ah[2], ah[3], bh[nt][0], bh[nt][1]);
                mma16816(acc[nt][0], acc[nt][1], acc[nt][2], acc[nt][3],
                         ah[0], ah[1], ah[2], ah[3], bl[nt][0], bl[nt][1]);
                mma16816(acc[nt][0], acc[nt][1], acc[nt][2], acc[nt][3],
                         al[0], al[1], al[2], al[3], bh[nt][0], bh[nt][1]);
            }
        }
        __syncthreads();
    }

    // epilogue: write raw out + BN partial sums
    const int g8 = lane >> 2, t4 = lane & 3;
    const int rA = row0 + warp * 16 + g8;       // row for c0,c1
    const int rB = rA + 8;                      // row for c2,c3
    float lsum[16], lsq[16];
    #pragma unroll
    for (int nt = 0; nt < 8; nt++) {
        int col = nt * 8 + 2 * t4;
        *(float2*)&g_raw[(size_t)rA * COUT + col] = make_float2(acc[nt][0], acc[nt][1]);
        *(float2*)&g_raw[(size_t)rB * COUT + col] = make_float2(acc[nt][2], acc[nt][3]);
        lsum[2 * nt]     = acc[nt][0] + acc[nt][2];
        lsum[2 * nt + 1] = acc[nt][1] + acc[nt][3];
        lsq[2 * nt]      = fmaf(acc[nt][0], acc[nt][0], acc[nt][2] * acc[nt][2]);
        lsq[2 * nt + 1]  = fmaf(acc[nt][1], acc[nt][1], acc[nt][3] * acc[nt][3]);
    }
    // reduce across the 8 row-groups (lanes sharing t4)
    #pragma unroll
    for (int mask = 4; mask <= 16; mask <<= 1) {
        #pragma unroll
        for (int v = 0; v < 16; v++) {
            lsum[v] += __shfl_xor_sync(0xffffffffu, lsum[v], mask);
            lsq[v]  += __shfl_xor_sync(0xffffffffu, lsq[v],  mask);
        }
    }
    if (g8 == 0) {
        #pragma unroll
        for (int nt = 0; nt < 8; nt++) {
            int col = nt * 8 + 2 * t4;
            atomicAdd(&sm_bn[col],            lsum[2 * nt]);
            atomicAdd(&sm_bn[col + 1],        lsum[2 * nt + 1]);
            atomicAdd(&sm_bn[COUT + col],     lsq[2 * nt]);
            atomicAdd(&sm_bn[COUT + col + 1], lsq[2 * nt + 1]);
        }
    }
    __syncthreads();
    if (tid < 2 * COUT) atomicAdd(&g_accum[tid], sm_bn[tid]);
}

// ================= BN stats + finalize =================
__global__ void bn_stats_kernel(const float* __restrict__ gamma,
                                const float* __restrict__ beta)
{
    int d = threadIdx.x;
    if (d >= COUT) return;
    const float invN = 1.0f / (float)NPTS;
    float mean = g_accum[d] * invN;
    float var  = g_accum[COUT + d] * invN - mean * mean;
    float inv  = 1.0f / sqrtf(var + BN_EPS);
    float sc   = gamma[d] * inv;
    g_params[d]        = sc;
    g_params[COUT + d] = fmaf(-mean, sc, beta[d]);
}

__global__ __launch_bounds__(256)
void finalize_kernel(float* __restrict__ out)
{
    int i = blockIdx.x * blockDim.x + threadIdx.x;   // over N*64/4 float4s
    float4 v = *(const float4*)&g_raw[(size_t)i * 4];
    int d4 = i & 15;
    const float4* p4 = (const float4*)g_params;
    float4 sc = p4[d4];
    float4 sh = p4[16 + d4];
    float x0 = fmaf(v.x, sc.x, sh.x);
    float x1 = fmaf(v.y, sc.y, sh.y);
    float x2 = fmaf(v.z, sc.z, sh.z);
    float x3 = fmaf(v.w, sc.w, sh.w);
    x0 = (x0 >= 0.f) ? x0 : NEG_SLOPE * x0;
    x1 = (x1 >= 0.f) ? x1 : NEG_SLOPE * x1;
    x2 = (x2 >= 0.f) ? x2 : NEG_SLOPE * x2;
    x3 = (x3 >= 0.f) ? x3 : NEG_SLOPE * x3;
    ((float4*)out)[i] = make_float4(x0, x1, x2, x3);
}

extern "C" void kernel_launch(void* const* d_in, const int* in_sizes, int n_in,
                              void* d_out, int out_size)
{
    const float* xyz    = (const float*)d_in[0];
    const float* feats  = (const float*)d_in[1];
    const int*   nbr    = (const int*)d_in[2];
    const float* weight = (const float*)d_in[3];
    const float* kpts   = (const float*)d_in[4];
    const float* gamma  = (const float*)d_in[5];
    const float* beta   = (const float*)d_in[6];
    float* out = (float*)d_out;

    kpconv_wf<<<NPTS / 8, 128>>>(xyz, feats, nbr, kpts, weight);
    gemm_kernel<<<NPTS / 128, 256>>>();
    bn_stats_kernel<<<1, 64>>>(gamma, beta);
    finalize_kernel<<<(NPTS * COUT / 4) / 256, 256>>>(out);
}